// round 1
// baseline (speedup 1.0000x reference)
#include <cuda_runtime.h>
#include <math.h>
#include <stdint.h>

#define BB 8
#define TT 16
#define CIN 32
#define HIDC 64
#define HH 64
#define WW 64
#define OC 256
#define HP 66
#define PP 4096        // 64*64
#define PIMG 4356      // 66*66
#define NPB (BB*HIDC*PP)        // per-step gate elements = 2,097,152
#define NOUT (BB*TT*HIDC*PP)    // total output elements = 33,554,432
#define CNTC (BB*TT*HH*WW)      // per-channel reduce count = 524,288

// ---------------- scratch (static device allocations; no cudaMalloc) ----------------
__device__ float g_xpad[(size_t)BB*TT*CIN*PIMG];   // padded x, ~71 MB
__device__ float g_hpad[(size_t)BB*HIDC*PIMG];     // padded h state, ~8.9 MB
__device__ float g_cst[(size_t)BB*HIDC*PP];        // c state, ~8.4 MB
__device__ float g_ccx[(size_t)BB*TT*OC*PP];       // precomputed conv_x(+bias), 512 MB
__device__ float g_cch[(size_t)BB*OC*PP];          // per-step conv_h, 33.5 MB
__device__ float g_wre[96*9*OC];                   // weights reordered [ic][tap][oc]
__device__ float g_ps[64*32*2];                    // partial sums (sum, sumsq)
__device__ float g_stat[128];                      // mean[64], rstd[64]

// ---------------- small prep kernels ----------------
__global__ void pad_x_k(const float* __restrict__ x) {
    int i = blockIdx.x*256 + threadIdx.x;
    if (i >= BB*TT*CIN*PP) return;
    int p  = i & (PP-1);
    int ch = i >> 12;              // (b*T + t)*CIN + c
    int y = p >> 6, xx = p & 63;
    g_xpad[(size_t)ch*PIMG + (size_t)(y+1)*HP + (xx+1)] = x[i];
}

__global__ void wre_k(const float* __restrict__ w) {
    int i = blockIdx.x*256 + threadIdx.x;
    if (i >= 96*9*OC) return;
    int oc  = i & 255;
    int tap = (i >> 8) % 9;
    int ic  = i / (9*256);
    // w: [256][96][3][3]
    g_wre[i] = w[(size_t)oc*(96*9) + (size_t)ic*9 + tap];
}

// ---------------- tiled direct conv (implicit GEMM) ----------------
// Block: 128 pixels (2 image rows) x 128 out-channels. Thread: 8 oc x 8 px.
template<int IC, bool BIAS>
__global__ void __launch_bounds__(256, 2) conv_k(
    const float* __restrict__ inp,   // [nimg][IC][66*66], zero-padded border
    const float* __restrict__ wre,   // [IC][9][256] (pre-offset for ic base)
    const float* __restrict__ bias,  // [256] or nullptr
    float* __restrict__ outc)        // [nimg][256][4096]
{
    __shared__ __align__(16) float sA[4][4][HP];    // 4 ic x 4 rows x 66
    __shared__ __align__(16) float sW[4][9][128];   // 4 ic x 9 taps x 128 oc

    const int tid = threadIdx.x;
    const int tx = tid & 15;        // oc octet
    const int ty = tid >> 4;        // pixel octet
    const int pr = ty >> 3;         // row within 2-row tile
    const int cb = (ty & 7) << 3;   // col base
    const int mt = blockIdx.x;      // 0..31  (2 output rows each)
    const int nt = blockIdx.y;      // 0..1
    const int img = blockIdx.z;
    const int r0 = mt << 1;
    const int n0 = nt << 7;

    const float* in0 = inp + (size_t)img*IC*PIMG;
    float* out0 = outc + (size_t)img*OC*PP;

    float acc[8][8];  // [o][j]
    #pragma unroll
    for (int o = 0; o < 8; ++o) {
        float bv = BIAS ? bias[n0 + tx*8 + o] : 0.f;
        #pragma unroll
        for (int j = 0; j < 8; ++j) acc[o][j] = bv;
    }

    for (int icc = 0; icc < IC; icc += 4) {
        __syncthreads();
        // load input tile: 4 ic x 4 padded rows x 66 cols
        for (int i = tid; i < 4*4*HP; i += 256) {
            int ic  = i / (4*HP);
            int rem = i - ic*(4*HP);
            int r   = rem / HP;
            int c   = rem - r*HP;
            sA[ic][r][c] = in0[(size_t)(icc+ic)*PIMG + (size_t)(r0+r)*HP + c];
        }
        // load weight tile: 4 ic x 9 taps x 128 oc (coalesced)
        for (int i = tid; i < 4*9*128; i += 256) {
            int ic  = i / 1152;
            int rem = i - ic*1152;
            int tap = rem >> 7;
            int oc  = rem & 127;
            sW[ic][tap][oc] = wre[(size_t)(icc+ic)*2304 + tap*256 + n0 + oc];
        }
        __syncthreads();

        #pragma unroll 1
        for (int ic = 0; ic < 4; ++ic) {
            #pragma unroll 1
            for (int ky = 0; ky < 3; ++ky) {
                float v[10];
                const float* ap = &sA[ic][pr+ky][cb];
                #pragma unroll
                for (int j = 0; j < 10; ++j) v[j] = ap[j];
                #pragma unroll
                for (int kx = 0; kx < 3; ++kx) {
                    const float4 w0 = *(const float4*)&sW[ic][ky*3+kx][tx*8];
                    const float4 w1 = *(const float4*)&sW[ic][ky*3+kx][tx*8+4];
                    const float wv[8] = {w0.x,w0.y,w0.z,w0.w,w1.x,w1.y,w1.z,w1.w};
                    #pragma unroll
                    for (int o = 0; o < 8; ++o)
                        #pragma unroll
                        for (int j = 0; j < 8; ++j)
                            acc[o][j] = fmaf(v[j+kx], wv[o], acc[o][j]);
                }
            }
        }
    }

    #pragma unroll
    for (int o = 0; o < 8; ++o) {
        float* dst = out0 + (size_t)(n0 + tx*8 + o)*PP + (size_t)(r0+pr)*WW + cb;
        *(float4*)(dst)   = make_float4(acc[o][0],acc[o][1],acc[o][2],acc[o][3]);
        *(float4*)(dst+4) = make_float4(acc[o][4],acc[o][5],acc[o][6],acc[o][7]);
    }
}

// ---------------- fused LSTM gates + state update + leaky relu ----------------
__global__ void gate_k(float* __restrict__ out, int t) {
    int i = blockIdx.x*256 + threadIdx.x;
    if (i >= NPB) return;
    int p   = i & (PP-1);
    int r   = i >> 12;
    int hid = r & 63;
    int b   = r >> 6;
    const size_t G = (size_t)HIDC*PP;
    size_t xb = (((size_t)b*TT + t)*OC + hid)*PP + p;
    size_t hb = ((size_t)b*OC + hid)*PP + p;

    float ci = g_ccx[xb]       + g_cch[hb];
    float cf = g_ccx[xb + G]   + g_cch[hb + G];
    float co = g_ccx[xb + 2*G] + g_cch[hb + 2*G];
    float cg = g_ccx[xb + 3*G] + g_cch[hb + 3*G];

    float si = 1.f/(1.f + expf(-ci));
    float sf = 1.f/(1.f + expf(-cf));
    float so = 1.f/(1.f + expf(-co));
    float tg = tanhf(cg);

    float cn = sf * g_cst[i] + si * tg;
    float hn = so * tanhf(cn);
    g_cst[i] = cn;

    int y = p >> 6, xx = p & 63;
    g_hpad[(size_t)(b*HIDC + hid)*PIMG + (size_t)(y+1)*HP + (xx+1)] = hn;
    out[(((size_t)b*TT + t)*HIDC + hid)*PP + p] = (hn >= 0.f) ? hn : 0.01f*hn;
}

// ---------------- deterministic two-stage normalization ----------------
__global__ void red1_k(const float* __restrict__ out) {
    int c = blockIdx.x;       // channel
    int s = blockIdx.y;       // slice 0..31
    float sum = 0.f, sq = 0.f;
    for (int k = 0; k < 64; ++k) {
        int e  = s*16384 + k*256 + threadIdx.x;   // element within channel
        int bt = e >> 12;
        int p  = e & (PP-1);
        float v = out[((size_t)bt*HIDC + c)*PP + p];
        sum += v; sq += v*v;
    }
    __shared__ float s1[256], s2[256];
    s1[threadIdx.x] = sum; s2[threadIdx.x] = sq;
    __syncthreads();
    for (int st = 128; st > 0; st >>= 1) {
        if (threadIdx.x < st) {
            s1[threadIdx.x] += s1[threadIdx.x+st];
            s2[threadIdx.x] += s2[threadIdx.x+st];
        }
        __syncthreads();
    }
    if (threadIdx.x == 0) {
        g_ps[(c*32+s)*2]   = s1[0];
        g_ps[(c*32+s)*2+1] = s2[0];
    }
}

__global__ void red2_k() {
    int c = threadIdx.x;  // 64 threads
    float sum = 0.f, sq = 0.f;
    for (int s = 0; s < 32; ++s) {
        sum += g_ps[(c*32+s)*2];
        sq  += g_ps[(c*32+s)*2+1];
    }
    float mean = sum / (float)CNTC;
    float var  = sq / (float)CNTC - mean*mean;
    var = var > 0.f ? var : 0.f;
    g_stat[c]    = mean;
    g_stat[64+c] = rsqrtf(var + 0.001f);
}

__global__ void norm_k(float* __restrict__ out,
                       const float* __restrict__ gamma,
                       const float* __restrict__ beta) {
    int i = blockIdx.x*256 + threadIdx.x;
    if (i >= NOUT) return;
    int c = (i >> 12) & 63;
    float v = out[i];
    out[i] = (v - g_stat[c]) * g_stat[64+c] * gamma[c] + beta[c];
}

// ---------------- launch ----------------
extern "C" void kernel_launch(void* const* d_in, const int* in_sizes, int n_in,
                              void* d_out, int out_size) {
    const float* x     = (const float*)d_in[0];
    const float* wconv = (const float*)d_in[1];
    const float* bconv = (const float*)d_in[2];
    const float* gamma = (const float*)d_in[3];
    const float* beta  = (const float*)d_in[4];
    float* out = (float*)d_out;

    float *xpad, *hpad, *cst, *ccx, *cch, *wre;
    cudaGetSymbolAddress((void**)&xpad, g_xpad);
    cudaGetSymbolAddress((void**)&hpad, g_hpad);
    cudaGetSymbolAddress((void**)&cst,  g_cst);
    cudaGetSymbolAddress((void**)&ccx,  g_ccx);
    cudaGetSymbolAddress((void**)&cch,  g_cch);
    cudaGetSymbolAddress((void**)&wre,  g_wre);

    // zero state + padded buffers (borders must be 0; graph-capturable memset nodes)
    cudaMemsetAsync(xpad, 0, sizeof(float)*(size_t)BB*TT*CIN*PIMG);
    cudaMemsetAsync(hpad, 0, sizeof(float)*(size_t)BB*HIDC*PIMG);
    cudaMemsetAsync(cst,  0, sizeof(float)*(size_t)BB*HIDC*PP);

    pad_x_k<<<(BB*TT*CIN*PP + 255)/256, 256>>>(x);
    wre_k<<<(96*9*OC + 255)/256, 256>>>(wconv);

    // parallel part: conv_x(+bias) for all B*T images at once
    conv_k<CIN, true><<<dim3(32, 2, BB*TT), 256>>>(xpad, wre, bconv, ccx);

    // sequential recurrence
    for (int t = 0; t < TT; ++t) {
        conv_k<HIDC, false><<<dim3(32, 2, BB), 256>>>(hpad, wre + 32*9*OC, nullptr, cch);
        gate_k<<<(NPB + 255)/256, 256>>>(out, t);
    }

    // normalization
    red1_k<<<dim3(64, 32), 256>>>(out);
    red2_k<<<1, 64>>>();
    norm_k<<<(NOUT + 255)/256, 256>>>(out, gamma, beta);
}

// round 7
// speedup vs baseline: 1.3377x; 1.3377x over previous
#include <cuda_runtime.h>
#include <cuda_bf16.h>
#include <math.h>
#include <stdint.h>

#define BB 8
#define TT 16
#define HIDC 64
#define PP 4096
#define PIMG 4356      // 66*66
#define NPB (BB*HIDC*PP)
#define NOUT (BB*TT*HIDC*PP)
#define CNTC (BB*TT*64*64)
#define NIMGX (BB*TT)

// ---------------- device scratch ----------------
__device__ __nv_bfloat16 g_x16[(size_t)NIMGX*PIMG*64];   // [img][px][hi32|lo32]
__device__ __nv_bfloat16 g_h16[(size_t)BB*PIMG*128];     // [b][px][hi64|lo64]
__device__ float g_hf[(size_t)BB*HIDC*PP];               // h fp32 [b][hid][px]
__device__ float g_cst[(size_t)BB*HIDC*PP];              // c state
__device__ float g_ccx[(size_t)NIMGX*256*PP];            // conv_x out (512 MB)
__device__ float g_cch[(size_t)BB*256*PP];               // conv_h out
__device__ __nv_bfloat16 g_wxB1[9*64*256];               // x pass1: [tap][k=64 (hi|hi)][oc]
__device__ __nv_bfloat16 g_wxB2[9*32*256];               // x pass2: [tap][k=32 (lo)][oc]
__device__ __nv_bfloat16 g_whB1[9*128*256];              // h pass1: [tap][k=128 (hi|hi)][oc]
__device__ __nv_bfloat16 g_whB2[9*64*256];               // h pass2: [tap][k=64 (lo)][oc]
__device__ float g_ps[64*32*2];
__device__ float g_stat[128];

// ---------------- PTX helpers (arch-neutral: ldmatrix + mma.sync) ----------------
__device__ __forceinline__ uint32_t smem_u32(const void* p) {
    uint32_t a;
    asm("{ .reg .u64 t; cvta.to.shared.u64 t, %1; cvt.u32.u64 %0, t; }" : "=r"(a) : "l"(p));
    return a;
}
__device__ __forceinline__ void ldsm_x4(uint32_t* r, uint32_t a) {
    asm volatile("ldmatrix.sync.aligned.m8n8.x4.shared.b16 {%0,%1,%2,%3}, [%4];"
                 : "=r"(r[0]), "=r"(r[1]), "=r"(r[2]), "=r"(r[3]) : "r"(a));
}
__device__ __forceinline__ void ldsm_x4t(uint32_t* r, uint32_t a) {
    asm volatile("ldmatrix.sync.aligned.m8n8.x4.trans.shared.b16 {%0,%1,%2,%3}, [%4];"
                 : "=r"(r[0]), "=r"(r[1]), "=r"(r[2]), "=r"(r[3]) : "r"(a));
}
__device__ __forceinline__ void mma16816(float* d, const uint32_t* a, uint32_t b0, uint32_t b1) {
    asm volatile(
        "mma.sync.aligned.m16n8k16.row.col.f32.bf16.bf16.f32 "
        "{%0,%1,%2,%3}, {%4,%5,%6,%7}, {%8,%9}, {%0,%1,%2,%3};"
        : "+f"(d[0]), "+f"(d[1]), "+f"(d[2]), "+f"(d[3])
        : "r"(a[0]), "r"(a[1]), "r"(a[2]), "r"(a[3]), "r"(b0), "r"(b1));
}

// ---------------- prep: x -> NHWC bf16 hi/lo (padded) ----------------
__global__ void prep_x_k(const float* __restrict__ x) {
    __shared__ float s[32][33];
    int pt = blockIdx.x, img = blockIdx.y;
    int p0 = pt * 32;
    for (int it = 0; it < 4; ++it) {
        int r = it * 8 + (threadIdx.x >> 5);
        s[r][threadIdx.x & 31] = x[((size_t)img*32 + r)*PP + p0 + (threadIdx.x & 31)];
    }
    __syncthreads();
    for (int it = 0; it < 8; ++it) {
        int o = it * 256 + threadIdx.x;     // 0..2047
        int pl = o >> 6, ch = o & 63;
        float v = s[ch & 31][pl];
        __nv_bfloat16 hi = __float2bfloat16(v);
        __nv_bfloat16 ov = (ch < 32) ? hi : __float2bfloat16(v - __bfloat162float(hi));
        int p = p0 + pl, y = p >> 6, xx = p & 63;
        g_x16[((size_t)img*PIMG + (size_t)(y+1)*66 + xx + 1)*64 + ch] = ov;
    }
}

// ---------------- prep: weights -> B tiles (pass1 [hi|hi], pass2 [lo]) ----------------
__global__ void prep_w_k(const float* __restrict__ w) {
    int i = blockIdx.x*256 + threadIdx.x;
    if (i >= 256*96*9) return;
    int tap = i % 9;
    int ic  = (i / 9) % 96;
    int oc  = i / (9*96);
    float v = w[(size_t)(oc*96 + ic)*9 + tap];
    __nv_bfloat16 hi = __float2bfloat16(v);
    __nv_bfloat16 lo = __float2bfloat16(v - __bfloat162float(hi));
    if (ic < 32) {
        g_wxB1[((size_t)tap*64 + ic)*256 + oc]      = hi;
        g_wxB1[((size_t)tap*64 + ic + 32)*256 + oc] = hi;
        g_wxB2[((size_t)tap*32 + ic)*256 + oc]      = lo;
    } else {
        int hc = ic - 32;
        g_whB1[((size_t)tap*128 + hc)*256 + oc]      = hi;
        g_whB1[((size_t)tap*128 + hc + 64)*256 + oc] = hi;
        g_whB2[((size_t)tap*64 + hc)*256 + oc]       = lo;
    }
}

// ---------------- HMMA implicit-GEMM conv (3-term bf16 split) ----------------
// CTA: 128 px (2 image rows) x 128 oc. 8 warps, warp tile 32(M) x 64(N).
// Per tap: pass1 A[hi|lo] x B1[hi|hi] (K=KC); pass2 A[hi] x B2[lo] (K=KC/2).
template<int KC>
__global__ void __launch_bounds__(256) conv_mma_k(
    const __nv_bfloat16* __restrict__ src,     // [img][66*66][KC]
    const __nv_bfloat16* __restrict__ wB1,     // [9][KC][256]
    const __nv_bfloat16* __restrict__ wB2,     // [9][KC/2][256]
    float* __restrict__ outc)                  // [img][256][4096]
{
    extern __shared__ __align__(128) char smem[];
    const int RBA = KC * 2;                     // A row bytes
    const int tid = threadIdx.x;
    const int wid = tid >> 5, lid = tid & 31;
    const int tile = blockIdx.x;                // 0..31
    const int by   = blockIdx.y;                // 0..1 (oc half)
    const int img  = blockIdx.z;
    const int r0 = tile * 2, p0 = tile * 128;
    const int mbase = (wid & 3) * 32;
    const int NW = (wid >> 2) * 64;
    const uint32_t sA  = smem_u32(smem);
    const uint32_t sB1 = sA + 128 * RBA;
    const uint32_t sB2 = sB1 + KC * 256;
    const uint32_t OFF_B1 = 128 * RBA;
    const uint32_t OFF_B2 = OFF_B1 + KC * 256;

    float acc[2][8][4];
    #pragma unroll
    for (int a = 0; a < 2; ++a)
        #pragma unroll
        for (int b = 0; b < 8; ++b)
            #pragma unroll
            for (int c = 0; c < 4; ++c) acc[a][b][c] = 0.f;

    const float4* srcv = (const float4*)(src + (size_t)img * PIMG * KC);

    for (int tap = 0; tap < 9; ++tap) {
        const int dy = tap / 3, dx = tap - dy*3;
        __syncthreads();
        // stage A: 128 px rows x KC ch (16B chunks, XOR swizzle)
        for (int c = tid; c < 128*(KC/8); c += 256) {
            int m = c / (KC/8), j = c % (KC/8);
            int pr = (r0 + (m >> 6) + dy)*66 + (m & 63) + dx;
            float4 v = srcv[(size_t)pr*(KC/8) + j];
            *(float4*)(smem + m*RBA + ((j*16) ^ ((m & 7) << 4))) = v;
        }
        // stage B1: KC rows x 128 oc
        for (int c = tid; c < KC*16; c += 256) {
            int k = c >> 4, j = c & 15;
            float4 v = ((const float4*)(wB1 + (size_t)(tap*KC + k)*256 + by*128))[j];
            *(float4*)(smem + OFF_B1 + k*256 + ((j*16) ^ ((k & 7) << 4))) = v;
        }
        // stage B2: KC/2 rows x 128 oc
        for (int c = tid; c < (KC/2)*16; c += 256) {
            int k = c >> 4, j = c & 15;
            float4 v = ((const float4*)(wB2 + (size_t)(tap*(KC/2) + k)*256 + by*128))[j];
            *(float4*)(smem + OFF_B2 + k*256 + ((j*16) ^ ((k & 7) << 4))) = v;
        }
        __syncthreads();

        // pass 1: full A (hi|lo) x B1 (hi|hi)
        #pragma unroll
        for (int ks = 0; ks < KC/16; ++ks) {
            uint32_t afr[2][4];
            #pragma unroll
            for (int mt = 0; mt < 2; ++mt) {
                int row = mbase + mt*16 + (lid & 15);
                uint32_t addr = sA + row*RBA + ((ks*32 + (lid >> 4)*16) ^ ((row & 7) << 4));
                ldsm_x4(afr[mt], addr);
            }
            uint32_t bfr[4][4];
            #pragma unroll
            for (int p = 0; p < 4; ++p) {
                int k = ks*16 + (lid & 15);
                uint32_t cb = (uint32_t)(NW + p*16)*2 + ((lid >> 4) << 4);
                uint32_t addr = sB1 + k*256 + (cb ^ ((k & 7) << 4));
                ldsm_x4t(bfr[p], addr);
            }
            #pragma unroll
            for (int mt = 0; mt < 2; ++mt)
                #pragma unroll
                for (int p = 0; p < 4; ++p) {
                    mma16816(acc[mt][p*2],     afr[mt], bfr[p][0], bfr[p][1]);
                    mma16816(acc[mt][p*2 + 1], afr[mt], bfr[p][2], bfr[p][3]);
                }
        }
        // pass 2: A hi half x B2 (lo)
        #pragma unroll
        for (int ks = 0; ks < KC/32; ++ks) {
            uint32_t afr[2][4];
            #pragma unroll
            for (int mt = 0; mt < 2; ++mt) {
                int row = mbase + mt*16 + (lid & 15);
                uint32_t addr = sA + row*RBA + ((ks*32 + (lid >> 4)*16) ^ ((row & 7) << 4));
                ldsm_x4(afr[mt], addr);
            }
            uint32_t bfr[4][4];
            #pragma unroll
            for (int p = 0; p < 4; ++p) {
                int k = ks*16 + (lid & 15);
                uint32_t cb = (uint32_t)(NW + p*16)*2 + ((lid >> 4) << 4);
                uint32_t addr = sB2 + k*256 + (cb ^ ((k & 7) << 4));
                ldsm_x4t(bfr[p], addr);
            }
            #pragma unroll
            for (int mt = 0; mt < 2; ++mt)
                #pragma unroll
                for (int p = 0; p < 4; ++p) {
                    mma16816(acc[mt][p*2],     afr[mt], bfr[p][0], bfr[p][1]);
                    mma16816(acc[mt][p*2 + 1], afr[mt], bfr[p][2], bfr[p][3]);
                }
        }
    }

    // epilogue: [oc][px]
    const int gid = lid >> 2, qid = lid & 3;
    float* outp = outc + (size_t)img*256*PP + (size_t)by*128*PP;
    #pragma unroll
    for (int mt = 0; mt < 2; ++mt)
        #pragma unroll
        for (int nt = 0; nt < 8; ++nt) {
            int n  = NW + nt*8 + qid*2;
            int px = p0 + mbase + mt*16 + gid;
            float* o0 = outp + (size_t)n*PP + px;
            o0[0]      = acc[mt][nt][0];
            o0[PP]     = acc[mt][nt][1];
            o0[8]      = acc[mt][nt][2];
            o0[PP + 8] = acc[mt][nt][3];
        }
}

// ---------------- fused gates + state update + leaky relu (+bias) ----------------
__global__ void gate_k(float* __restrict__ out, const float* __restrict__ bconv, int t) {
    int i = blockIdx.x*256 + threadIdx.x;
    if (i >= NPB) return;
    int p   = i & (PP-1);
    int r   = i >> 12;
    int hid = r & 63;
    int b   = r >> 6;
    const size_t G = (size_t)HIDC*PP;
    size_t xb = (((size_t)b*TT + t)*256 + hid)*PP + p;
    size_t hb = ((size_t)b*256 + hid)*PP + p;

    float ci = g_ccx[xb]       + g_cch[hb]       + bconv[hid];
    float cf = g_ccx[xb + G]   + g_cch[hb + G]   + bconv[64 + hid];
    float co = g_ccx[xb + 2*G] + g_cch[hb + 2*G] + bconv[128 + hid];
    float cg = g_ccx[xb + 3*G] + g_cch[hb + 3*G] + bconv[192 + hid];

    float si = 1.f/(1.f + expf(-ci));
    float sf = 1.f/(1.f + expf(-cf));
    float so = 1.f/(1.f + expf(-co));
    float tg = tanhf(cg);

    float cn = sf * g_cst[i] + si * tg;
    float hn = so * tanhf(cn);
    g_cst[i] = cn;
    g_hf[i]  = hn;
    out[(((size_t)b*TT + t)*HIDC + hid)*PP + p] = (hn >= 0.f) ? hn : 0.01f*hn;
}

// ---------------- pack h fp32 -> NHWC bf16 hi/lo (padded) ----------------
__global__ void pack_h_k() {
    __shared__ float s[64][33];
    int pt = blockIdx.x, b = blockIdx.y;
    int p0 = pt * 32;
    for (int it = 0; it < 8; ++it) {
        int r = it * 8 + (threadIdx.x >> 5);
        s[r][threadIdx.x & 31] = g_hf[((size_t)b*64 + r)*PP + p0 + (threadIdx.x & 31)];
    }
    __syncthreads();
    for (int it = 0; it < 16; ++it) {
        int o = it * 256 + threadIdx.x;   // 0..4095
        int pl = o >> 7, ch = o & 127;
        float v = s[ch & 63][pl];
        __nv_bfloat16 hi = __float2bfloat16(v);
        __nv_bfloat16 ov = (ch < 64) ? hi : __float2bfloat16(v - __bfloat162float(hi));
        int p = p0 + pl, y = p >> 6, xx = p & 63;
        g_h16[((size_t)b*PIMG + (size_t)(y+1)*66 + xx + 1)*128 + ch] = ov;
    }
}

// ---------------- deterministic two-stage normalization ----------------
__global__ void red1_k(const float* __restrict__ out) {
    int c = blockIdx.x, s = blockIdx.y;
    float sum = 0.f, sq = 0.f;
    for (int k = 0; k < 64; ++k) {
        int e  = s*16384 + k*256 + threadIdx.x;
        int bt = e >> 12;
        int p  = e & (PP-1);
        float v = out[((size_t)bt*HIDC + c)*PP + p];
        sum += v; sq += v*v;
    }
    __shared__ float s1[256], s2[256];
    s1[threadIdx.x] = sum; s2[threadIdx.x] = sq;
    __syncthreads();
    for (int st = 128; st > 0; st >>= 1) {
        if (threadIdx.x < st) {
            s1[threadIdx.x] += s1[threadIdx.x+st];
            s2[threadIdx.x] += s2[threadIdx.x+st];
        }
        __syncthreads();
    }
    if (threadIdx.x == 0) {
        g_ps[(c*32+s)*2]   = s1[0];
        g_ps[(c*32+s)*2+1] = s2[0];
    }
}

__global__ void red2_k() {
    int c = threadIdx.x;
    float sum = 0.f, sq = 0.f;
    for (int s = 0; s < 32; ++s) { sum += g_ps[(c*32+s)*2]; sq += g_ps[(c*32+s)*2+1]; }
    float mean = sum / (float)CNTC;
    float var  = sq / (float)CNTC - mean*mean;
    var = var > 0.f ? var : 0.f;
    g_stat[c]    = mean;
    g_stat[64+c] = rsqrtf(var + 0.001f);
}

__global__ void norm_k(float* __restrict__ out,
                       const float* __restrict__ gamma,
                       const float* __restrict__ beta) {
    int i = blockIdx.x*256 + threadIdx.x;
    if (i >= NOUT) return;
    int c = (i >> 12) & 63;
    float v = out[i];
    out[i] = (v - g_stat[c]) * g_stat[64+c] * gamma[c] + beta[c];
}

// ---------------- launch ----------------
extern "C" void kernel_launch(void* const* d_in, const int* in_sizes, int n_in,
                              void* d_out, int out_size) {
    const float* x     = (const float*)d_in[0];
    const float* wconv = (const float*)d_in[1];
    const float* bconv = (const float*)d_in[2];
    const float* gamma = (const float*)d_in[3];
    const float* beta  = (const float*)d_in[4];
    float* out = (float*)d_out;

    void *x16, *h16, *cst, *ccx, *cch, *wxB1, *wxB2, *whB1, *whB2;
    cudaGetSymbolAddress(&x16, g_x16);
    cudaGetSymbolAddress(&h16, g_h16);
    cudaGetSymbolAddress(&cst, g_cst);
    cudaGetSymbolAddress(&ccx, g_ccx);
    cudaGetSymbolAddress(&cch, g_cch);
    cudaGetSymbolAddress(&wxB1, g_wxB1);
    cudaGetSymbolAddress(&wxB2, g_wxB2);
    cudaGetSymbolAddress(&whB1, g_whB1);
    cudaGetSymbolAddress(&whB2, g_whB2);

    cudaFuncSetAttribute(conv_mma_k<64>,  cudaFuncAttributeMaxDynamicSharedMemorySize, 40960);
    cudaFuncSetAttribute(conv_mma_k<128>, cudaFuncAttributeMaxDynamicSharedMemorySize, 81920);

    // zero padded planes + c state (borders must be 0)
    cudaMemsetAsync(x16, 0, sizeof(__nv_bfloat16)*(size_t)NIMGX*PIMG*64);
    cudaMemsetAsync(h16, 0, sizeof(__nv_bfloat16)*(size_t)BB*PIMG*128);
    cudaMemsetAsync(cst, 0, sizeof(float)*(size_t)BB*HIDC*PP);

    prep_x_k<<<dim3(128, NIMGX), 256>>>(x);
    prep_w_k<<<(256*96*9 + 255)/256, 256>>>(wconv);

    // conv_x for all B*T images
    conv_mma_k<64><<<dim3(32, 2, NIMGX), 256, 40960>>>(
        (const __nv_bfloat16*)x16, (const __nv_bfloat16*)g_wxB1 ? (const __nv_bfloat16*)wxB1 : nullptr,
        (const __nv_bfloat16*)wxB2, (float*)ccx);

    // recurrence
    for (int t = 0; t < TT; ++t) {
        conv_mma_k<128><<<dim3(32, 2, BB), 256, 81920>>>(
            (const __nv_bfloat16*)h16, (const __nv_bfloat16*)whB1,
            (const __nv_bfloat16*)whB2, (float*)cch);
        gate_k<<<(NPB + 255)/256, 256>>>(out, bconv, t);
        pack_h_k<<<dim3(128, BB), 256>>>();
    }

    // normalization
    red1_k<<<dim3(64, 32), 256>>>(out);
    red2_k<<<1, 64>>>();
    norm_k<<<(NOUT + 255)/256, 256>>>(out, gamma, beta);
}

// round 8
// speedup vs baseline: 2.4186x; 1.8081x over previous
#include <cuda_runtime.h>
#include <cuda_bf16.h>
#include <math.h>
#include <stdint.h>

#define BB 8
#define TT 16
#define HIDC 64
#define PP 4096
#define PIMG 4356      // 66*66
#define NOUT (BB*TT*HIDC*PP)
#define CNTC (BB*TT*64*64)
#define NIMGX (BB*TT)

// ---------------- device scratch ----------------
__device__ __nv_bfloat16 g_x16[(size_t)NIMGX*PIMG*64];   // [img][px][hi32|lo32]
__device__ __nv_bfloat16 g_h16[(size_t)BB*PIMG*128];     // [b][px][hi64|lo64]
__device__ float g_cst[(size_t)BB*HIDC*PP];              // c state
__device__ float g_ccx[(size_t)NIMGX*256*PP];            // conv_x out (512 MB)
__device__ float g_cch[(size_t)BB*256*PP];               // conv_h out
__device__ __nv_bfloat16 g_wxB1[9*64*256];               // x pass1: [tap][k=64 (hi|hi)][oc]
__device__ __nv_bfloat16 g_wxB2[9*32*256];               // x pass2: [tap][k=32 (lo)][oc]
__device__ __nv_bfloat16 g_whB1[9*128*256];              // h pass1: [tap][k=128 (hi|hi)][oc]
__device__ __nv_bfloat16 g_whB2[9*64*256];               // h pass2: [tap][k=64 (lo)][oc]
__device__ float g_ps[64*32*2];
__device__ float g_stat[128];

// ---------------- PTX helpers (arch-neutral) ----------------
__device__ __forceinline__ uint32_t smem_u32(const void* p) {
    uint32_t a;
    asm("{ .reg .u64 t; cvta.to.shared.u64 t, %1; cvt.u32.u64 %0, t; }" : "=r"(a) : "l"(p));
    return a;
}
__device__ __forceinline__ void ldsm_x4(uint32_t* r, uint32_t a) {
    asm volatile("ldmatrix.sync.aligned.m8n8.x4.shared.b16 {%0,%1,%2,%3}, [%4];"
                 : "=r"(r[0]), "=r"(r[1]), "=r"(r[2]), "=r"(r[3]) : "r"(a));
}
__device__ __forceinline__ void ldsm_x4t(uint32_t* r, uint32_t a) {
    asm volatile("ldmatrix.sync.aligned.m8n8.x4.trans.shared.b16 {%0,%1,%2,%3}, [%4];"
                 : "=r"(r[0]), "=r"(r[1]), "=r"(r[2]), "=r"(r[3]) : "r"(a));
}
__device__ __forceinline__ void mma16816(float* d, const uint32_t* a, uint32_t b0, uint32_t b1) {
    asm volatile(
        "mma.sync.aligned.m16n8k16.row.col.f32.bf16.bf16.f32 "
        "{%0,%1,%2,%3}, {%4,%5,%6,%7}, {%8,%9}, {%0,%1,%2,%3};"
        : "+f"(d[0]), "+f"(d[1]), "+f"(d[2]), "+f"(d[3])
        : "r"(a[0]), "r"(a[1]), "r"(a[2]), "r"(a[3]), "r"(b0), "r"(b1));
}
__device__ __forceinline__ void cpa16(uint32_t dst, const void* src) {
    asm volatile("cp.async.ca.shared.global [%0], [%1], 16;" :: "r"(dst), "l"(src));
}
#define CPA_COMMIT() asm volatile("cp.async.commit_group;" ::: "memory")
#define CPA_WAIT0()  asm volatile("cp.async.wait_group 0;" ::: "memory")

// ---------------- prep: x -> NHWC bf16 hi/lo (padded) ----------------
__global__ void prep_x_k(const float* __restrict__ x) {
    __shared__ float s[32][33];
    int pt = blockIdx.x, img = blockIdx.y;
    int p0 = pt * 32;
    for (int it = 0; it < 4; ++it) {
        int r = it * 8 + (threadIdx.x >> 5);
        s[r][threadIdx.x & 31] = x[((size_t)img*32 + r)*PP + p0 + (threadIdx.x & 31)];
    }
    __syncthreads();
    for (int it = 0; it < 8; ++it) {
        int o = it * 256 + threadIdx.x;     // 0..2047
        int pl = o >> 6, ch = o & 63;
        float v = s[ch & 31][pl];
        __nv_bfloat16 hi = __float2bfloat16(v);
        __nv_bfloat16 ov = (ch < 32) ? hi : __float2bfloat16(v - __bfloat162float(hi));
        int p = p0 + pl, y = p >> 6, xx = p & 63;
        g_x16[((size_t)img*PIMG + (size_t)(y+1)*66 + xx + 1)*64 + ch] = ov;
    }
}

// ---------------- prep: weights -> B tiles (pass1 [hi|hi], pass2 [lo]) ----------------
__global__ void prep_w_k(const float* __restrict__ w) {
    int i = blockIdx.x*256 + threadIdx.x;
    if (i >= 256*96*9) return;
    int tap = i % 9;
    int ic  = (i / 9) % 96;
    int oc  = i / (9*96);
    float v = w[(size_t)(oc*96 + ic)*9 + tap];
    __nv_bfloat16 hi = __float2bfloat16(v);
    __nv_bfloat16 lo = __float2bfloat16(v - __bfloat162float(hi));
    if (ic < 32) {
        g_wxB1[((size_t)tap*64 + ic)*256 + oc]      = hi;
        g_wxB1[((size_t)tap*64 + ic + 32)*256 + oc] = hi;
        g_wxB2[((size_t)tap*32 + ic)*256 + oc]      = lo;
    } else {
        int hc = ic - 32;
        g_whB1[((size_t)tap*128 + hc)*256 + oc]      = hi;
        g_whB1[((size_t)tap*128 + hc + 64)*256 + oc] = hi;
        g_whB2[((size_t)tap*64 + hc)*256 + oc]       = lo;
    }
}

// ---------------- B staging (cp.async into swizzled buffer) ----------------
template<int KC>
__device__ __forceinline__ void stage_B(uint32_t bufb,
                                        const __nv_bfloat16* __restrict__ wB1,
                                        const __nv_bfloat16* __restrict__ wB2,
                                        int tap, int by, int tid) {
    const int NB1 = KC * 16;
    for (int c = tid; c < KC * 24; c += 256) {
        uint32_t dst; const __nv_bfloat16* src;
        if (c < NB1) {
            int k = c >> 4, j = c & 15;
            dst = bufb + k*256 + ((j*16) ^ ((k & 7) << 4));
            src = wB1 + (size_t)(tap*KC + k)*256 + by*128 + j*8;
        } else {
            int c2 = c - NB1;
            int k = c2 >> 4, j = c2 & 15;
            dst = bufb + KC*256 + k*256 + ((j*16) ^ ((k & 7) << 4));
            src = wB2 + (size_t)(tap*(KC/2) + k)*256 + by*128 + j*8;
        }
        cpa16(dst, src);
    }
}

// ---------------- MMA pass over one B tile ----------------
template<int RBA, int NKS>
__device__ __forceinline__ void do_pass(uint32_t sA, uint32_t sB, int dy, int dx,
                                        int mbase, int NW, int lid,
                                        float (&acc)[2][8][4]) {
    #pragma unroll
    for (int ks = 0; ks < NKS; ++ks) {
        uint32_t afr[2][4];
        #pragma unroll
        for (int mt = 0; mt < 2; ++mt) {
            int m = mbase + mt*16 + (lid & 15);
            int row = ((m >> 6) + dy)*66 + (m & 63) + dx;
            uint32_t addr = sA + row*RBA + ((ks*32 + (lid >> 4)*16) ^ ((row & 7) << 4));
            ldsm_x4(afr[mt], addr);
        }
        uint32_t bfr[4][4];
        #pragma unroll
        for (int p = 0; p < 4; ++p) {
            int k = ks*16 + (lid & 15);
            uint32_t cb = (uint32_t)(NW + p*16)*2 + ((lid >> 4) << 4);
            uint32_t addr = sB + k*256 + (cb ^ ((k & 7) << 4));
            ldsm_x4t(bfr[p], addr);
        }
        #pragma unroll
        for (int mt = 0; mt < 2; ++mt)
            #pragma unroll
            for (int p = 0; p < 4; ++p) {
                mma16816(acc[mt][p*2],     afr[mt], bfr[p][0], bfr[p][1]);
                mma16816(acc[mt][p*2 + 1], afr[mt], bfr[p][2], bfr[p][3]);
            }
    }
}

// ---------------- HMMA implicit-GEMM conv (3-term split, pipelined) ----------------
// CTA: 128 px x 128 oc. A staged ONCE (264 padded rows); B double-buffered cp.async.
template<int KC>
__global__ void __launch_bounds__(256, 1) conv_mma_k(
    const __nv_bfloat16* __restrict__ src,     // [img][66*66][KC]
    const __nv_bfloat16* __restrict__ wB1,     // [9][KC][256]
    const __nv_bfloat16* __restrict__ wB2,     // [9][KC/2][256]
    float* __restrict__ outc)                  // [img][256][4096]
{
    extern __shared__ __align__(128) char smem[];
    const int RBA = KC * 2;                     // A row bytes
    const int AROWS = 264;                      // 4 padded rows x 66 cols
    const uint32_t OFFB = AROWS * RBA;
    const uint32_t BSZ  = KC * 384;             // B1 + B2 bytes
    const int tid = threadIdx.x;
    const int wid = tid >> 5, lid = tid & 31;
    const int tile = blockIdx.x;                // 0..31
    const int by   = blockIdx.y;                // 0..1 (oc half)
    const int img  = blockIdx.z;
    const int r0 = tile * 2, p0 = tile * 128;
    const int mbase = (wid & 3) * 32;
    const int NW = (wid >> 2) * 64;
    const uint32_t sA = smem_u32(smem);

    const float4* srcv = (const float4*)(src + (size_t)img * PIMG * KC);

    // stage A once: 264 rows x KC ch (16B chunks, XOR swizzle)
    for (int c = tid; c < AROWS*(KC/8); c += 256) {
        int r = c / (KC/8), j = c % (KC/8);
        cpa16(sA + r*RBA + ((j*16) ^ ((r & 7) << 4)),
              srcv + (size_t)(r0*66 + r)*(KC/8) + j);
    }
    stage_B<KC>(sA + OFFB, wB1, wB2, 0, by, tid);
    CPA_COMMIT();
    CPA_WAIT0();
    __syncthreads();

    float acc[2][8][4];
    #pragma unroll
    for (int a = 0; a < 2; ++a)
        #pragma unroll
        for (int b = 0; b < 8; ++b)
            #pragma unroll
            for (int c = 0; c < 4; ++c) acc[a][b][c] = 0.f;

    for (int tap = 0; tap < 9; ++tap) {
        const int dy = tap / 3, dx = tap - dy*3;
        const int cur = tap & 1;
        if (tap < 8) {
            stage_B<KC>(sA + OFFB + (cur ^ 1)*BSZ, wB1, wB2, tap + 1, by, tid);
            CPA_COMMIT();
        }
        const uint32_t sB1 = sA + OFFB + cur*BSZ;
        const uint32_t sB2 = sB1 + KC*256;
        do_pass<KC*2, KC/16>(sA, sB1, dy, dx, mbase, NW, lid, acc);
        do_pass<KC*2, KC/32>(sA, sB2, dy, dx, mbase, NW, lid, acc);
        CPA_WAIT0();
        __syncthreads();
    }

    // epilogue: [oc][px]
    const int gid = lid >> 2, qid = lid & 3;
    float* outp = outc + (size_t)img*256*PP + (size_t)by*128*PP;
    #pragma unroll
    for (int mt = 0; mt < 2; ++mt)
        #pragma unroll
        for (int nt = 0; nt < 8; ++nt) {
            int n  = NW + nt*8 + qid*2;
            int px = p0 + mbase + mt*16 + gid;
            float* o0 = outp + (size_t)n*PP + px;
            o0[0]      = acc[mt][nt][0];
            o0[PP]     = acc[mt][nt][1];
            o0[8]      = acc[mt][nt][2];
            o0[PP + 8] = acc[mt][nt][3];
        }
}

// ---------------- fused gates + state + leaky relu + h repack ----------------
__global__ void gatepack_k(float* __restrict__ out, const float* __restrict__ bconv, int t) {
    __shared__ float sh[64][33];
    int pt = blockIdx.x;     // 0..127 (32-px tiles)
    int b  = blockIdx.y;
    int p0 = pt * 32;
    int tid = threadIdx.x;
    const size_t G = (size_t)HIDC*PP;

    #pragma unroll
    for (int it = 0; it < 8; ++it) {
        int idx = it*256 + tid;            // 0..2047
        int hid = idx >> 5;
        int px  = p0 + (idx & 31);
        size_t xb = (((size_t)b*TT + t)*256 + hid)*PP + px;
        size_t hb = ((size_t)b*256 + hid)*PP + px;

        float ci = g_ccx[xb]       + g_cch[hb]       + bconv[hid];
        float cf = g_ccx[xb + G]   + g_cch[hb + G]   + bconv[64 + hid];
        float co = g_ccx[xb + 2*G] + g_cch[hb + 2*G] + bconv[128 + hid];
        float cg = g_ccx[xb + 3*G] + g_cch[hb + 3*G] + bconv[192 + hid];

        float si = 1.f/(1.f + expf(-ci));
        float sf = 1.f/(1.f + expf(-cf));
        float so = 1.f/(1.f + expf(-co));
        float tg = tanhf(cg);

        size_t ii = ((size_t)(b*HIDC + hid))*PP + px;
        float cn = sf * g_cst[ii] + si * tg;
        float hn = so * tanhf(cn);
        g_cst[ii] = cn;
        out[(((size_t)b*TT + t)*HIDC + hid)*PP + px] = (hn >= 0.f) ? hn : 0.01f*hn;
        sh[hid][idx & 31] = hn;
    }
    __syncthreads();
    #pragma unroll
    for (int it = 0; it < 16; ++it) {
        int o = it*256 + tid;              // 0..4095
        int pl = o >> 7, ch = o & 127;
        float v = sh[ch & 63][pl];
        __nv_bfloat16 hi = __float2bfloat16(v);
        __nv_bfloat16 ov = (ch < 64) ? hi : __float2bfloat16(v - __bfloat162float(hi));
        int p = p0 + pl, y = p >> 6, xx = p & 63;
        g_h16[((size_t)b*PIMG + (size_t)(y+1)*66 + xx + 1)*128 + ch] = ov;
    }
}

// ---------------- deterministic two-stage normalization ----------------
__global__ void red1_k(const float* __restrict__ out) {
    int c = blockIdx.x, s = blockIdx.y;
    float sum = 0.f, sq = 0.f;
    for (int k = 0; k < 64; ++k) {
        int e  = s*16384 + k*256 + threadIdx.x;
        int bt = e >> 12;
        int p  = e & (PP-1);
        float v = out[((size_t)bt*HIDC + c)*PP + p];
        sum += v; sq += v*v;
    }
    __shared__ float s1[256], s2[256];
    s1[threadIdx.x] = sum; s2[threadIdx.x] = sq;
    __syncthreads();
    for (int st = 128; st > 0; st >>= 1) {
        if (threadIdx.x < st) {
            s1[threadIdx.x] += s1[threadIdx.x+st];
            s2[threadIdx.x] += s2[threadIdx.x+st];
        }
        __syncthreads();
    }
    if (threadIdx.x == 0) {
        g_ps[(c*32+s)*2]   = s1[0];
        g_ps[(c*32+s)*2+1] = s2[0];
    }
}

__global__ void red2_k() {
    int c = threadIdx.x;
    float sum = 0.f, sq = 0.f;
    for (int s = 0; s < 32; ++s) { sum += g_ps[(c*32+s)*2]; sq += g_ps[(c*32+s)*2+1]; }
    float mean = sum / (float)CNTC;
    float var  = sq / (float)CNTC - mean*mean;
    var = var > 0.f ? var : 0.f;
    g_stat[c]    = mean;
    g_stat[64+c] = rsqrtf(var + 0.001f);
}

__global__ void norm_k(float* __restrict__ out,
                       const float* __restrict__ gamma,
                       const float* __restrict__ beta) {
    int i = blockIdx.x*256 + threadIdx.x;
    if (i >= NOUT) return;
    int c = (i >> 12) & 63;
    float v = out[i];
    out[i] = (v - g_stat[c]) * g_stat[64+c] * gamma[c] + beta[c];
}

// ---------------- launch ----------------
extern "C" void kernel_launch(void* const* d_in, const int* in_sizes, int n_in,
                              void* d_out, int out_size) {
    const float* x     = (const float*)d_in[0];
    const float* wconv = (const float*)d_in[1];
    const float* bconv = (const float*)d_in[2];
    const float* gamma = (const float*)d_in[3];
    const float* beta  = (const float*)d_in[4];
    float* out = (float*)d_out;

    void *x16, *h16, *cst, *ccx, *cch, *wxB1, *wxB2, *whB1, *whB2;
    cudaGetSymbolAddress(&x16, g_x16);
    cudaGetSymbolAddress(&h16, g_h16);
    cudaGetSymbolAddress(&cst, g_cst);
    cudaGetSymbolAddress(&ccx, g_ccx);
    cudaGetSymbolAddress(&cch, g_cch);
    cudaGetSymbolAddress(&wxB1, g_wxB1);
    cudaGetSymbolAddress(&wxB2, g_wxB2);
    cudaGetSymbolAddress(&whB1, g_whB1);
    cudaGetSymbolAddress(&whB2, g_whB2);

    cudaFuncSetAttribute(conv_mma_k<64>,  cudaFuncAttributeMaxDynamicSharedMemorySize, 82944);
    cudaFuncSetAttribute(conv_mma_k<128>, cudaFuncAttributeMaxDynamicSharedMemorySize, 165888);

    // zero padded planes + c state (borders must be 0)
    cudaMemsetAsync(x16, 0, sizeof(__nv_bfloat16)*(size_t)NIMGX*PIMG*64);
    cudaMemsetAsync(h16, 0, sizeof(__nv_bfloat16)*(size_t)BB*PIMG*128);
    cudaMemsetAsync(cst, 0, sizeof(float)*(size_t)BB*HIDC*PP);

    prep_x_k<<<dim3(128, NIMGX), 256>>>(x);
    prep_w_k<<<(256*96*9 + 255)/256, 256>>>(wconv);

    // conv_x for all B*T images
    conv_mma_k<64><<<dim3(32, 2, NIMGX), 256, 82944>>>(
        (const __nv_bfloat16*)x16, (const __nv_bfloat16*)wxB1,
        (const __nv_bfloat16*)wxB2, (float*)ccx);

    // recurrence
    for (int t = 0; t < TT; ++t) {
        conv_mma_k<128><<<dim3(32, 2, BB), 256, 165888>>>(
            (const __nv_bfloat16*)h16, (const __nv_bfloat16*)whB1,
            (const __nv_bfloat16*)whB2, (float*)cch);
        gatepack_k<<<dim3(128, BB), 256>>>(out, bconv, t);
    }

    // normalization
    red1_k<<<dim3(64, 32), 256>>>(out);
    red2_k<<<1, 64>>>();
    norm_k<<<(NOUT + 255)/256, 256>>>(out, gamma, beta);
}

// round 10
// speedup vs baseline: 2.6795x; 1.1079x over previous
#include <cuda_runtime.h>
#include <cuda_bf16.h>
#include <math.h>
#include <stdint.h>

#define BB 8
#define TT 16
#define HIDC 64
#define PP 4096
#define PIMG 4356      // 66*66
#define NOUT (BB*TT*HIDC*PP)
#define CNTC (BB*TT*64*64)
#define NIMGX (BB*TT)

// ---------------- device scratch ----------------
__device__ __nv_bfloat16 g_x16[(size_t)NIMGX*PIMG*64];   // [img][px][hi32|lo32]
__device__ __nv_bfloat16 g_h16[(size_t)BB*PIMG*128];     // [b][px][hi64|lo64]
__device__ float g_cst[(size_t)BB*HIDC*PP];              // c state
__device__ float g_ccx[(size_t)NIMGX*256*PP];            // conv_x out (512 MB)
__device__ float g_cch[(size_t)BB*256*PP];               // conv_h out
__device__ __nv_bfloat16 g_wxB1[9*64*256];               // x pass1: [tap][k=64 (hi|hi)][oc]
__device__ __nv_bfloat16 g_wxB2[9*32*256];               // x pass2: [tap][k=32 (lo)][oc]
__device__ __nv_bfloat16 g_whB1[9*128*256];              // h pass1: [tap][k=128 (hi|hi)][oc]
__device__ __nv_bfloat16 g_whB2[9*64*256];               // h pass2: [tap][k=64 (lo)][oc]
__device__ float g_ps[64*32*2];
__device__ float g_stat[128];

// ---------------- PTX helpers (arch-neutral) ----------------
__device__ __forceinline__ uint32_t smem_u32(const void* p) {
    uint32_t a;
    asm("{ .reg .u64 t; cvta.to.shared.u64 t, %1; cvt.u32.u64 %0, t; }" : "=r"(a) : "l"(p));
    return a;
}
__device__ __forceinline__ void ldsm_x4(uint32_t* r, uint32_t a) {
    asm volatile("ldmatrix.sync.aligned.m8n8.x4.shared.b16 {%0,%1,%2,%3}, [%4];"
                 : "=r"(r[0]), "=r"(r[1]), "=r"(r[2]), "=r"(r[3]) : "r"(a));
}
__device__ __forceinline__ void ldsm_x4t(uint32_t* r, uint32_t a) {
    asm volatile("ldmatrix.sync.aligned.m8n8.x4.trans.shared.b16 {%0,%1,%2,%3}, [%4];"
                 : "=r"(r[0]), "=r"(r[1]), "=r"(r[2]), "=r"(r[3]) : "r"(a));
}
__device__ __forceinline__ void mma16816(float* d, const uint32_t* a, uint32_t b0, uint32_t b1) {
    asm volatile(
        "mma.sync.aligned.m16n8k16.row.col.f32.bf16.bf16.f32 "
        "{%0,%1,%2,%3}, {%4,%5,%6,%7}, {%8,%9}, {%0,%1,%2,%3};"
        : "+f"(d[0]), "+f"(d[1]), "+f"(d[2]), "+f"(d[3])
        : "r"(a[0]), "r"(a[1]), "r"(a[2]), "r"(a[3]), "r"(b0), "r"(b1));
}
__device__ __forceinline__ void cpa16(uint32_t dst, const void* src) {
    asm volatile("cp.async.ca.shared.global [%0], [%1], 16;" :: "r"(dst), "l"(src));
}
#define CPA_COMMIT() asm volatile("cp.async.commit_group;" ::: "memory")
#define CPA_WAIT0()  asm volatile("cp.async.wait_group 0;" ::: "memory")

// ---------------- prep: x -> NHWC bf16 hi/lo (padded) ----------------
__global__ void prep_x_k(const float* __restrict__ x) {
    __shared__ float s[32][33];
    int pt = blockIdx.x, img = blockIdx.y;
    int p0 = pt * 32;
    for (int it = 0; it < 4; ++it) {
        int r = it * 8 + (threadIdx.x >> 5);
        s[r][threadIdx.x & 31] = x[((size_t)img*32 + r)*PP + p0 + (threadIdx.x & 31)];
    }
    __syncthreads();
    for (int it = 0; it < 8; ++it) {
        int o = it * 256 + threadIdx.x;     // 0..2047
        int pl = o >> 6, ch = o & 63;
        float v = s[ch & 31][pl];
        __nv_bfloat16 hi = __float2bfloat16(v);
        __nv_bfloat16 ov = (ch < 32) ? hi : __float2bfloat16(v - __bfloat162float(hi));
        int p = p0 + pl, y = p >> 6, xx = p & 63;
        g_x16[((size_t)img*PIMG + (size_t)(y+1)*66 + xx + 1)*64 + ch] = ov;
    }
}

// ---------------- prep: weights -> B tiles (pass1 [hi|hi], pass2 [lo]) ----------------
__global__ void prep_w_k(const float* __restrict__ w) {
    int i = blockIdx.x*256 + threadIdx.x;
    if (i >= 256*96*9) return;
    int tap = i % 9;
    int ic  = (i / 9) % 96;
    int oc  = i / (9*96);
    float v = w[(size_t)(oc*96 + ic)*9 + tap];
    __nv_bfloat16 hi = __float2bfloat16(v);
    __nv_bfloat16 lo = __float2bfloat16(v - __bfloat162float(hi));
    if (ic < 32) {
        g_wxB1[((size_t)tap*64 + ic)*256 + oc]      = hi;
        g_wxB1[((size_t)tap*64 + ic + 32)*256 + oc] = hi;
        g_wxB2[((size_t)tap*32 + ic)*256 + oc]      = lo;
    } else {
        int hc = ic - 32;
        g_whB1[((size_t)tap*128 + hc)*256 + oc]      = hi;
        g_whB1[((size_t)tap*128 + hc + 64)*256 + oc] = hi;
        g_whB2[((size_t)tap*64 + hc)*256 + oc]       = lo;
    }
}

// ---------------- B staging (cp.async into swizzled buffer) ----------------
template<int KC>
__device__ __forceinline__ void stage_B(uint32_t bufb,
                                        const __nv_bfloat16* __restrict__ wB1,
                                        const __nv_bfloat16* __restrict__ wB2,
                                        int tap, int by, int tid) {
    const int NB1 = KC * 16;
    for (int c = tid; c < KC * 24; c += 256) {
        uint32_t dst; const __nv_bfloat16* src;
        if (c < NB1) {
            int k = c >> 4, j = c & 15;
            dst = bufb + k*256 + ((j*16) ^ ((k & 7) << 4));
            src = wB1 + (size_t)(tap*KC + k)*256 + by*128 + j*8;
        } else {
            int c2 = c - NB1;
            int k = c2 >> 4, j = c2 & 15;
            dst = bufb + KC*256 + k*256 + ((j*16) ^ ((k & 7) << 4));
            src = wB2 + (size_t)(tap*(KC/2) + k)*256 + by*128 + j*8;
        }
        cpa16(dst, src);
    }
}

// ---------------- MMA pass over one B tile (warp tile 64x64) ----------------
template<int RBA, int NKS>
__device__ __forceinline__ void do_pass(uint32_t sA, uint32_t sB, int dy, int dx,
                                        int mwarp, int nwarp, int lid,
                                        float (&acc)[4][8][4]) {
    #pragma unroll
    for (int ks = 0; ks < NKS; ++ks) {
        uint32_t afr[4][4];
        #pragma unroll
        for (int mt = 0; mt < 4; ++mt) {
            int m = mwarp + mt*16 + (lid & 15);
            int row = ((m >> 6) + dy)*66 + (m & 63) + dx;
            uint32_t addr = sA + row*RBA + ((ks*32 + (lid >> 4)*16) ^ ((row & 7) << 4));
            ldsm_x4(afr[mt], addr);
        }
        uint32_t bfr[4][4];
        #pragma unroll
        for (int p = 0; p < 4; ++p) {
            int k = ks*16 + (lid & 15);
            uint32_t cb = (uint32_t)(nwarp + p*16)*2 + ((lid >> 4) << 4);
            uint32_t addr = sB + k*256 + (cb ^ ((k & 7) << 4));
            ldsm_x4t(bfr[p], addr);
        }
        #pragma unroll
        for (int mt = 0; mt < 4; ++mt)
            #pragma unroll
            for (int p = 0; p < 4; ++p) {
                mma16816(acc[mt][p*2],     afr[mt], bfr[p][0], bfr[p][1]);
                mma16816(acc[mt][p*2 + 1], afr[mt], bfr[p][2], bfr[p][3]);
            }
    }
}

// ---------------- HMMA implicit-GEMM conv (3-term split, pipelined) ----------------
// CTA: 256 px (4 output rows) x 128 oc, 8 warps, warp tile 64x64.
// A staged ONCE (6 padded rows = 396); B double-buffered cp.async over taps.
template<int KC>
__global__ void __launch_bounds__(256) conv_mma_k(
    const __nv_bfloat16* __restrict__ src,     // [img][66*66][KC]
    const __nv_bfloat16* __restrict__ wB1,     // [9][KC][256]
    const __nv_bfloat16* __restrict__ wB2,     // [9][KC/2][256]
    float* __restrict__ outc)                  // [img][256][4096]
{
    extern __shared__ __align__(128) char smem[];
    const int RBA = KC * 2;                     // A row bytes
    const int AROWS = 396;                      // 6 padded rows x 66 cols
    const uint32_t OFFB = AROWS * RBA;
    const uint32_t BSZ  = KC * 384;             // B1 + B2 bytes
    const int tid = threadIdx.x;
    const int wid = tid >> 5, lid = tid & 31;
    const int tile = blockIdx.x;                // 0..15
    const int by   = blockIdx.y;                // 0..1 (oc half)
    const int img  = blockIdx.z;
    const int r0 = tile * 4, p0 = tile * 256;
    const int mwarp = (wid & 3) * 64;
    const int nwarp = (wid >> 2) * 64;
    const uint32_t sA = smem_u32(smem);

    const float4* srcv = (const float4*)(src + (size_t)img * PIMG * KC);

    // stage A once: 396 rows x KC ch (16B chunks, XOR swizzle)
    for (int c = tid; c < AROWS*(KC/8); c += 256) {
        int r = c / (KC/8), j = c % (KC/8);
        cpa16(sA + r*RBA + ((j*16) ^ ((r & 7) << 4)),
              srcv + (size_t)(r0*66 + r)*(KC/8) + j);
    }
    stage_B<KC>(sA + OFFB, wB1, wB2, 0, by, tid);
    CPA_COMMIT();
    CPA_WAIT0();
    __syncthreads();

    float acc[4][8][4];
    #pragma unroll
    for (int a = 0; a < 4; ++a)
        #pragma unroll
        for (int b = 0; b < 8; ++b)
            #pragma unroll
            for (int c = 0; c < 4; ++c) acc[a][b][c] = 0.f;

    for (int tap = 0; tap < 9; ++tap) {
        const int dy = tap / 3, dx = tap - dy*3;
        const int cur = tap & 1;
        if (tap < 8) {
            stage_B<KC>(sA + OFFB + (cur ^ 1)*BSZ, wB1, wB2, tap + 1, by, tid);
            CPA_COMMIT();
        }
        const uint32_t sB1 = sA + OFFB + cur*BSZ;
        const uint32_t sB2 = sB1 + KC*256;
        do_pass<KC*2, KC/16>(sA, sB1, dy, dx, mwarp, nwarp, lid, acc);
        do_pass<KC*2, KC/32>(sA, sB2, dy, dx, mwarp, nwarp, lid, acc);
        CPA_WAIT0();
        __syncthreads();
    }

    // epilogue: [oc][px]
    const int gid = lid >> 2, qid = lid & 3;
    float* outp = outc + (size_t)img*256*PP + (size_t)by*128*PP;
    #pragma unroll
    for (int mt = 0; mt < 4; ++mt)
        #pragma unroll
        for (int nt = 0; nt < 8; ++nt) {
            int n  = nwarp + nt*8 + qid*2;
            int px = p0 + mwarp + mt*16 + gid;
            float* o0 = outp + (size_t)n*PP + px;
            o0[0]      = acc[mt][nt][0];
            o0[PP]     = acc[mt][nt][1];
            o0[8]      = acc[mt][nt][2];
            o0[PP + 8] = acc[mt][nt][3];
        }
}

// ---------------- fused gates + state + leaky relu + h repack ----------------
__global__ void gatepack_k(float* __restrict__ out, const float* __restrict__ bconv, int t) {
    __shared__ float sh[64][33];
    int pt = blockIdx.x;     // 0..127 (32-px tiles)
    int b  = blockIdx.y;
    int p0 = pt * 32;
    int tid = threadIdx.x;
    const size_t G = (size_t)HIDC*PP;

    #pragma unroll
    for (int it = 0; it < 8; ++it) {
        int idx = it*256 + tid;            // 0..2047
        int hid = idx >> 5;
        int px  = p0 + (idx & 31);
        size_t xb = (((size_t)b*TT + t)*256 + hid)*PP + px;
        size_t hb = ((size_t)b*256 + hid)*PP + px;

        float ci = g_ccx[xb]       + g_cch[hb]       + bconv[hid];
        float cf = g_ccx[xb + G]   + g_cch[hb + G]   + bconv[64 + hid];
        float co = g_ccx[xb + 2*G] + g_cch[hb + 2*G] + bconv[128 + hid];
        float cg = g_ccx[xb + 3*G] + g_cch[hb + 3*G] + bconv[192 + hid];

        float si = 1.f/(1.f + expf(-ci));
        float sf = 1.f/(1.f + expf(-cf));
        float so = 1.f/(1.f + expf(-co));
        float tg = tanhf(cg);

        size_t ii = ((size_t)(b*HIDC + hid))*PP + px;
        float cn = sf * g_cst[ii] + si * tg;
        float hn = so * tanhf(cn);
        g_cst[ii] = cn;
        out[(((size_t)b*TT + t)*HIDC + hid)*PP + px] = (hn >= 0.f) ? hn : 0.01f*hn;
        sh[hid][idx & 31] = hn;
    }
    __syncthreads();
    #pragma unroll
    for (int it = 0; it < 16; ++it) {
        int o = it*256 + tid;              // 0..4095
        int pl = o >> 7, ch = o & 127;
        float v = sh[ch & 63][pl];
        __nv_bfloat16 hi = __float2bfloat16(v);
        __nv_bfloat16 ov = (ch < 64) ? hi : __float2bfloat16(v - __bfloat162float(hi));
        int p = p0 + pl, y = p >> 6, xx = p & 63;
        g_h16[((size_t)b*PIMG + (size_t)(y+1)*66 + xx + 1)*128 + ch] = ov;
    }
}

// ---------------- deterministic two-stage normalization ----------------
__global__ void red1_k(const float* __restrict__ out) {
    int c = blockIdx.x, s = blockIdx.y;
    float sum = 0.f, sq = 0.f;
    for (int k = 0; k < 64; ++k) {
        int e  = s*16384 + k*256 + threadIdx.x;
        int bt = e >> 12;
        int p  = e & (PP-1);
        float v = out[((size_t)bt*HIDC + c)*PP + p];
        sum += v; sq += v*v;
    }
    __shared__ float s1[256], s2[256];
    s1[threadIdx.x] = sum; s2[threadIdx.x] = sq;
    __syncthreads();
    for (int st = 128; st > 0; st >>= 1) {
        if (threadIdx.x < st) {
            s1[threadIdx.x] += s1[threadIdx.x+st];
            s2[threadIdx.x] += s2[threadIdx.x+st];
        }
        __syncthreads();
    }
    if (threadIdx.x == 0) {
        g_ps[(c*32+s)*2]   = s1[0];
        g_ps[(c*32+s)*2+1] = s2[0];
    }
}

__global__ void red2_k() {
    int c = threadIdx.x;
    float sum = 0.f, sq = 0.f;
    for (int s = 0; s < 32; ++s) { sum += g_ps[(c*32+s)*2]; sq += g_ps[(c*32+s)*2+1]; }
    float mean = sum / (float)CNTC;
    float var  = sq / (float)CNTC - mean*mean;
    var = var > 0.f ? var : 0.f;
    g_stat[c]    = mean;
    g_stat[64+c] = rsqrtf(var + 0.001f);
}

__global__ void norm_k(float* __restrict__ out,
                       const float* __restrict__ gamma,
                       const float* __restrict__ beta) {
    int i = blockIdx.x*256 + threadIdx.x;
    if (i >= NOUT) return;
    int c = (i >> 12) & 63;
    float v = out[i];
    out[i] = (v - g_stat[c]) * g_stat[64+c] * gamma[c] + beta[c];
}

// ---------------- launch ----------------
extern "C" void kernel_launch(void* const* d_in, const int* in_sizes, int n_in,
                              void* d_out, int out_size) {
    const float* x     = (const float*)d_in[0];
    const float* wconv = (const float*)d_in[1];
    const float* bconv = (const float*)d_in[2];
    const float* gamma = (const float*)d_in[3];
    const float* beta  = (const float*)d_in[4];
    float* out = (float*)d_out;

    void *x16, *h16, *cst, *ccx, *cch, *wxB1, *wxB2, *whB1, *whB2;
    cudaGetSymbolAddress(&x16, g_x16);
    cudaGetSymbolAddress(&h16, g_h16);
    cudaGetSymbolAddress(&cst, g_cst);
    cudaGetSymbolAddress(&ccx, g_ccx);
    cudaGetSymbolAddress(&cch, g_cch);
    cudaGetSymbolAddress(&wxB1, g_wxB1);
    cudaGetSymbolAddress(&wxB2, g_wxB2);
    cudaGetSymbolAddress(&whB1, g_whB1);
    cudaGetSymbolAddress(&whB2, g_whB2);

    // smem: A(396*KC*2) + 2*(KC*384)
    cudaFuncSetAttribute(conv_mma_k<64>,  cudaFuncAttributeMaxDynamicSharedMemorySize, 99840);
    cudaFuncSetAttribute(conv_mma_k<128>, cudaFuncAttributeMaxDynamicSharedMemorySize, 199680);

    // zero padded planes + c state (borders must be 0)
    cudaMemsetAsync(x16, 0, sizeof(__nv_bfloat16)*(size_t)NIMGX*PIMG*64);
    cudaMemsetAsync(h16, 0, sizeof(__nv_bfloat16)*(size_t)BB*PIMG*128);
    cudaMemsetAsync(cst, 0, sizeof(float)*(size_t)BB*HIDC*PP);

    prep_x_k<<<dim3(128, NIMGX), 256>>>(x);
    prep_w_k<<<(256*96*9 + 255)/256, 256>>>(wconv);

    // conv_x for all B*T images
    conv_mma_k<64><<<dim3(16, 2, NIMGX), 256, 99840>>>(
        (const __nv_bfloat16*)x16, (const __nv_bfloat16*)wxB1,
        (const __nv_bfloat16*)wxB2, (float*)ccx);

    // recurrence
    for (int t = 0; t < TT; ++t) {
        conv_mma_k<128><<<dim3(16, 2, BB), 256, 199680>>>(
            (const __nv_bfloat16*)h16, (const __nv_bfloat16*)whB1,
            (const __nv_bfloat16*)whB2, (float*)cch);
        gatepack_k<<<dim3(128, BB), 256>>>(out, bconv, t);
    }

    // normalization
    red1_k<<<dim3(64, 32), 256>>>(out);
    red2_k<<<1, 64>>>();
    norm_k<<<(NOUT + 255)/256, 256>>>(out, gamma, beta);
}

// round 13
// speedup vs baseline: 2.8601x; 1.0674x over previous
#include <cuda_runtime.h>
#include <cuda_bf16.h>
#include <math.h>
#include <stdint.h>

#define BB 8
#define TT 16
#define HIDC 64
#define PP 4096
#define PIMG 4356      // 66*66
#define NOUT (BB*TT*HIDC*PP)
#define CNTC (BB*TT*64*64)
#define NIMGX (BB*TT)

// ---------------- device scratch ----------------
__device__ __nv_bfloat16 g_x16[(size_t)NIMGX*PIMG*64];   // [img][px][hi32|lo32]
__device__ __nv_bfloat16 g_h16[(size_t)BB*PIMG*128];     // [b][px][hi64|lo64]
__device__ float g_cst[(size_t)BB*HIDC*PP];              // c state
__device__ float g_ccx[(size_t)NIMGX*256*PP];            // conv_x out (512 MB)
__device__ float g_cch[(size_t)BB*256*PP];               // conv_h out
__device__ __nv_bfloat16 g_wxB1[9*64*256];               // x pass1: [tap][k=64 (hi|hi)][oc]
__device__ __nv_bfloat16 g_wxB2[9*32*256];               // x pass2: [tap][k=32 (lo)][oc]
__device__ __nv_bfloat16 g_whB1[9*128*256];              // h pass1: [tap][k=128 (hi|hi)][oc]
__device__ __nv_bfloat16 g_whB2[9*64*256];               // h pass2: [tap][k=64 (lo)][oc]
__device__ float g_ps[64*32*2];
__device__ float g_stat[128];

// ---------------- PTX helpers (arch-neutral) ----------------
__device__ __forceinline__ uint32_t smem_u32(const void* p) {
    uint32_t a;
    asm("{ .reg .u64 t; cvta.to.shared.u64 t, %1; cvt.u32.u64 %0, t; }" : "=r"(a) : "l"(p));
    return a;
}
__device__ __forceinline__ void ldsm_x4(uint32_t* r, uint32_t a) {
    asm volatile("ldmatrix.sync.aligned.m8n8.x4.shared.b16 {%0,%1,%2,%3}, [%4];"
                 : "=r"(r[0]), "=r"(r[1]), "=r"(r[2]), "=r"(r[3]) : "r"(a));
}
__device__ __forceinline__ void ldsm_x4t(uint32_t* r, uint32_t a) {
    asm volatile("ldmatrix.sync.aligned.m8n8.x4.trans.shared.b16 {%0,%1,%2,%3}, [%4];"
                 : "=r"(r[0]), "=r"(r[1]), "=r"(r[2]), "=r"(r[3]) : "r"(a));
}
__device__ __forceinline__ void mma16816(float* d, const uint32_t* a, uint32_t b0, uint32_t b1) {
    asm volatile(
        "mma.sync.aligned.m16n8k16.row.col.f32.bf16.bf16.f32 "
        "{%0,%1,%2,%3}, {%4,%5,%6,%7}, {%8,%9}, {%0,%1,%2,%3};"
        : "+f"(d[0]), "+f"(d[1]), "+f"(d[2]), "+f"(d[3])
        : "r"(a[0]), "r"(a[1]), "r"(a[2]), "r"(a[3]), "r"(b0), "r"(b1));
}
__device__ __forceinline__ void cpa16(uint32_t dst, const void* src) {
    asm volatile("cp.async.ca.shared.global [%0], [%1], 16;" :: "r"(dst), "l"(src));
}
#define CPA_COMMIT() asm volatile("cp.async.commit_group;" ::: "memory")
#define CPA_WAIT0()  asm volatile("cp.async.wait_group 0;" ::: "memory")

// ---------------- prep: x -> NHWC bf16 hi/lo (padded) ----------------
__global__ void prep_x_k(const float* __restrict__ x) {
    __shared__ float s[32][33];
    int pt = blockIdx.x, img = blockIdx.y;
    int p0 = pt * 32;
    for (int it = 0; it < 4; ++it) {
        int r = it * 8 + (threadIdx.x >> 5);
        s[r][threadIdx.x & 31] = x[((size_t)img*32 + r)*PP + p0 + (threadIdx.x & 31)];
    }
    __syncthreads();
    for (int it = 0; it < 8; ++it) {
        int o = it * 256 + threadIdx.x;     // 0..2047
        int pl = o >> 6, ch = o & 63;
        float v = s[ch & 31][pl];
        __nv_bfloat16 hi = __float2bfloat16(v);
        __nv_bfloat16 ov = (ch < 32) ? hi : __float2bfloat16(v - __bfloat162float(hi));
        int p = p0 + pl, y = p >> 6, xx = p & 63;
        g_x16[((size_t)img*PIMG + (size_t)(y+1)*66 + xx + 1)*64 + ch] = ov;
    }
}

// ---------------- prep: weights -> B tiles (pass1 [hi|hi], pass2 [lo]) ----------------
__global__ void prep_w_k(const float* __restrict__ w) {
    int i = blockIdx.x*256 + threadIdx.x;
    if (i >= 256*96*9) return;
    int tap = i % 9;
    int ic  = (i / 9) % 96;
    int oc  = i / (9*96);
    float v = w[(size_t)(oc*96 + ic)*9 + tap];
    __nv_bfloat16 hi = __float2bfloat16(v);
    __nv_bfloat16 lo = __float2bfloat16(v - __bfloat162float(hi));
    if (ic < 32) {
        g_wxB1[((size_t)tap*64 + ic)*256 + oc]      = hi;
        g_wxB1[((size_t)tap*64 + ic + 32)*256 + oc] = hi;
        g_wxB2[((size_t)tap*32 + ic)*256 + oc]      = lo;
    } else {
        int hc = ic - 32;
        g_whB1[((size_t)tap*128 + hc)*256 + oc]      = hi;
        g_whB1[((size_t)tap*128 + hc + 64)*256 + oc] = hi;
        g_whB2[((size_t)tap*64 + hc)*256 + oc]       = lo;
    }
}

// ---------------- B staging (cp.async into swizzled buffer) ----------------
template<int KC>
__device__ __forceinline__ void stage_B(uint32_t bufb,
                                        const __nv_bfloat16* __restrict__ wB1,
                                        const __nv_bfloat16* __restrict__ wB2,
                                        int tap, int by, int tid) {
    const int NB1 = KC * 16;
    for (int c = tid; c < KC * 24; c += 256) {
        uint32_t dst; const __nv_bfloat16* src;
        if (c < NB1) {
            int k = c >> 4, j = c & 15;
            dst = bufb + k*256 + ((j*16) ^ ((k & 7) << 4));
            src = wB1 + (size_t)(tap*KC + k)*256 + by*128 + j*8;
        } else {
            int c2 = c - NB1;
            int k = c2 >> 4, j = c2 & 15;
            dst = bufb + KC*256 + k*256 + ((j*16) ^ ((k & 7) << 4));
            src = wB2 + (size_t)(tap*(KC/2) + k)*256 + by*128 + j*8;
        }
        cpa16(dst, src);
    }
}

// ---------------- MMA pass over one B tile (warp tile 64x64, low reg pressure) ----------------
template<int RBA, int NKS>
__device__ __forceinline__ void do_pass(uint32_t sA, uint32_t sB, int dy, int dx,
                                        int mwarp, int nwarp, int lid,
                                        float (&acc)[4][8][4]) {
    // B swizzle is lane-constant: k = ks*16 + (lid&15), so k&7 = lid&7.
    uint32_t bBase[4];
    #pragma unroll
    for (int p = 0; p < 4; ++p) {
        int k0 = lid & 15;
        uint32_t cb = (uint32_t)(nwarp + p*16)*2 + ((lid >> 4) << 4);
        bBase[p] = sB + k0*256 + (cb ^ ((k0 & 7) << 4));
    }
    #pragma unroll
    for (int ks = 0; ks < NKS; ++ks) {
        uint32_t afr[4][4];
        #pragma unroll
        for (int mt = 0; mt < 4; ++mt) {
            int m = mwarp + mt*16 + (lid & 15);
            int row = ((m >> 6) + dy)*66 + (m & 63) + dx;
            uint32_t addr = sA + row*RBA + ((ks*32 + (lid >> 4)*16) ^ ((row & 7) << 4));
            ldsm_x4(afr[mt], addr);
        }
        #pragma unroll
        for (int p = 0; p < 4; ++p) {
            uint32_t bfr[4];
            ldsm_x4t(bfr, bBase[p] + (uint32_t)ks*4096);
            #pragma unroll
            for (int mt = 0; mt < 4; ++mt) {
                mma16816(acc[mt][p*2],     afr[mt], bfr[0], bfr[1]);
                mma16816(acc[mt][p*2 + 1], afr[mt], bfr[2], bfr[3]);
            }
        }
    }
}

// ---------------- HMMA implicit-GEMM conv (3-term split, pipelined) ----------------
// CTA: 256 px (4 output rows) x 128 oc, 8 warps, warp tile 64x64.
// A staged ONCE (6 padded rows = 396); B double-buffered cp.async over taps.
// img = blockIdx.z * img_mul + img_add  (lets conv_x run per-timestep chunks).
template<int KC>
__global__ void __launch_bounds__(256) conv_mma_k(
    const __nv_bfloat16* __restrict__ src,     // [img][66*66][KC]
    const __nv_bfloat16* __restrict__ wB1,     // [9][KC][256]
    const __nv_bfloat16* __restrict__ wB2,     // [9][KC/2][256]
    float* __restrict__ outc,                  // [img][256][4096]
    int img_mul, int img_add)
{
    extern __shared__ __align__(128) char smem[];
    const int RBA = KC * 2;                     // A row bytes
    const int AROWS = 396;                      // 6 padded rows x 66 cols
    const uint32_t OFFB = AROWS * RBA;
    const uint32_t BSZ  = KC * 384;             // B1 + B2 bytes
    const int tid = threadIdx.x;
    const int wid = tid >> 5, lid = tid & 31;
    const int tile = blockIdx.x;                // 0..15
    const int by   = blockIdx.y;                // 0..1 (oc half)
    const int img  = blockIdx.z * img_mul + img_add;
    const int r0 = tile * 4, p0 = tile * 256;
    const int mwarp = (wid & 3) * 64;
    const int nwarp = (wid >> 2) * 64;
    const uint32_t sA = smem_u32(smem);

    const float4* srcv = (const float4*)(src + (size_t)img * PIMG * KC);

    // stage A once: 396 rows x KC ch (16B chunks, XOR swizzle)
    for (int c = tid; c < AROWS*(KC/8); c += 256) {
        int r = c / (KC/8), j = c % (KC/8);
        cpa16(sA + r*RBA + ((j*16) ^ ((r & 7) << 4)),
              srcv + (size_t)(r0*66 + r)*(KC/8) + j);
    }
    stage_B<KC>(sA + OFFB, wB1, wB2, 0, by, tid);
    CPA_COMMIT();
    CPA_WAIT0();
    __syncthreads();

    float acc[4][8][4];
    #pragma unroll
    for (int a = 0; a < 4; ++a)
        #pragma unroll
        for (int b = 0; b < 8; ++b)
            #pragma unroll
            for (int c = 0; c < 4; ++c) acc[a][b][c] = 0.f;

    for (int tap = 0; tap < 9; ++tap) {
        const int dy = tap / 3, dx = tap - dy*3;
        const int cur = tap & 1;
        if (tap < 8) {
            stage_B<KC>(sA + OFFB + (cur ^ 1)*BSZ, wB1, wB2, tap + 1, by, tid);
            CPA_COMMIT();
        }
        const uint32_t sB1 = sA + OFFB + cur*BSZ;
        const uint32_t sB2 = sB1 + KC*256;
        do_pass<KC*2, KC/16>(sA, sB1, dy, dx, mwarp, nwarp, lid, acc);
        do_pass<KC*2, KC/32>(sA, sB2, dy, dx, mwarp, nwarp, lid, acc);
        CPA_WAIT0();
        __syncthreads();
    }

    // epilogue: [oc][px]
    const int gid = lid >> 2, qid = lid & 3;
    float* outp = outc + (size_t)img*256*PP + (size_t)by*128*PP;
    #pragma unroll
    for (int mt = 0; mt < 4; ++mt)
        #pragma unroll
        for (int nt = 0; nt < 8; ++nt) {
            int n  = nwarp + nt*8 + qid*2;
            int px = p0 + mwarp + mt*16 + gid;
            float* o0 = outp + (size_t)n*PP + px;
            o0[0]      = acc[mt][nt][0];
            o0[PP]     = acc[mt][nt][1];
            o0[8]      = acc[mt][nt][2];
            o0[PP + 8] = acc[mt][nt][3];
        }
}

// ---------------- fused gates + state + leaky relu + h repack (fast exp) ----------------
__device__ __forceinline__ float fsigmoid(float x) { return 1.f/(1.f + __expf(-x)); }
__device__ __forceinline__ float ftanh(float x)    { return 1.f - 2.f/(__expf(2.f*x) + 1.f); }

__global__ void gatepack_k(float* __restrict__ out, const float* __restrict__ bconv, int t) {
    __shared__ float sh[64][33];
    int pt = blockIdx.x;     // 0..127 (32-px tiles)
    int b  = blockIdx.y;
    int p0 = pt * 32;
    int tid = threadIdx.x;
    const size_t G = (size_t)HIDC*PP;

    #pragma unroll
    for (int it = 0; it < 8; ++it) {
        int idx = it*256 + tid;            // 0..2047
        int hid = idx >> 5;
        int px  = p0 + (idx & 31);
        size_t xb = (((size_t)b*TT + t)*256 + hid)*PP + px;
        size_t hb = ((size_t)b*256 + hid)*PP + px;

        float ci = g_ccx[xb]       + g_cch[hb]       + bconv[hid];
        float cf = g_ccx[xb + G]   + g_cch[hb + G]   + bconv[64 + hid];
        float co = g_ccx[xb + 2*G] + g_cch[hb + 2*G] + bconv[128 + hid];
        float cg = g_ccx[xb + 3*G] + g_cch[hb + 3*G] + bconv[192 + hid];

        float si = fsigmoid(ci);
        float sf = fsigmoid(cf);
        float so = fsigmoid(co);
        float tg = ftanh(cg);

        size_t ii = ((size_t)(b*HIDC + hid))*PP + px;
        float cn = sf * g_cst[ii] + si * tg;
        float hn = so * ftanh(cn);
        g_cst[ii] = cn;
        out[(((size_t)b*TT + t)*HIDC + hid)*PP + px] = (hn >= 0.f) ? hn : 0.01f*hn;
        sh[hid][idx & 31] = hn;
    }
    __syncthreads();
    #pragma unroll
    for (int it = 0; it < 16; ++it) {
        int o = it*256 + tid;              // 0..4095
        int pl = o >> 7, ch = o & 127;
        float v = sh[ch & 63][pl];
        __nv_bfloat16 hi = __float2bfloat16(v);
        __nv_bfloat16 ov = (ch < 64) ? hi : __float2bfloat16(v - __bfloat162float(hi));
        int p = p0 + pl, y = p >> 6, xx = p & 63;
        g_h16[((size_t)b*PIMG + (size_t)(y+1)*66 + xx + 1)*128 + ch] = ov;
    }
}

// ---------------- deterministic two-stage normalization ----------------
__global__ void red1_k(const float* __restrict__ out) {
    int c = blockIdx.x, s = blockIdx.y;
    float sum = 0.f, sq = 0.f;
    for (int k = 0; k < 64; ++k) {
        int e  = s*16384 + k*256 + threadIdx.x;
        int bt = e >> 12;
        int p  = e & (PP-1);
        float v = out[((size_t)bt*HIDC + c)*PP + p];
        sum += v; sq += v*v;
    }
    __shared__ float s1[256], s2[256];
    s1[threadIdx.x] = sum; s2[threadIdx.x] = sq;
    __syncthreads();
    for (int st = 128; st > 0; st >>= 1) {
        if (threadIdx.x < st) {
            s1[threadIdx.x] += s1[threadIdx.x+st];
            s2[threadIdx.x] += s2[threadIdx.x+st];
        }
        __syncthreads();
    }
    if (threadIdx.x == 0) {
        g_ps[(c*32+s)*2]   = s1[0];
        g_ps[(c*32+s)*2+1] = s2[0];
    }
}

__global__ void red2_k() {
    int c = threadIdx.x;
    float sum = 0.f, sq = 0.f;
    for (int s = 0; s < 32; ++s) { sum += g_ps[(c*32+s)*2]; sq += g_ps[(c*32+s)*2+1]; }
    float mean = sum / (float)CNTC;
    float var  = sq / (float)CNTC - mean*mean;
    var = var > 0.f ? var : 0.f;
    g_stat[c]    = mean;
    g_stat[64+c] = rsqrtf(var + 0.001f);
}

__global__ void norm_k(float* __restrict__ out,
                       const float* __restrict__ gamma,
                       const float* __restrict__ beta) {
    int i = blockIdx.x*256 + threadIdx.x;
    if (i >= NOUT) return;
    int c = (i >> 12) & 63;
    float v = out[i];
    out[i] = (v - g_stat[c]) * g_stat[64+c] * gamma[c] + beta[c];
}

// ---------------- launch ----------------
extern "C" void kernel_launch(void* const* d_in, const int* in_sizes, int n_in,
                              void* d_out, int out_size) {
    const float* x     = (const float*)d_in[0];
    const float* wconv = (const float*)d_in[1];
    const float* bconv = (const float*)d_in[2];
    const float* gamma = (const float*)d_in[3];
    const float* beta  = (const float*)d_in[4];
    float* out = (float*)d_out;

    void *x16, *h16, *cst, *ccx, *cch, *wxB1, *wxB2, *whB1, *whB2;
    cudaGetSymbolAddress(&x16, g_x16);
    cudaGetSymbolAddress(&h16, g_h16);
    cudaGetSymbolAddress(&cst, g_cst);
    cudaGetSymbolAddress(&ccx, g_ccx);
    cudaGetSymbolAddress(&cch, g_cch);
    cudaGetSymbolAddress(&wxB1, g_wxB1);
    cudaGetSymbolAddress(&wxB2, g_wxB2);
    cudaGetSymbolAddress(&whB1, g_whB1);
    cudaGetSymbolAddress(&whB2, g_whB2);

    // one-time host objects (created on the uncaptured correctness call)
    static cudaStream_t s2 = nullptr;
    static cudaEvent_t evFork = nullptr;
    static cudaEvent_t evX[TT];
    if (!s2) {
        int leastPri = 0, greatestPri = 0;
        cudaDeviceGetStreamPriorityRange(&leastPri, &greatestPri);
        cudaStreamCreateWithPriority(&s2, cudaStreamNonBlocking, leastPri);
        cudaEventCreateWithFlags(&evFork, cudaEventDisableTiming);
        for (int t = 0; t < TT; ++t) cudaEventCreateWithFlags(&evX[t], cudaEventDisableTiming);
    }

    // smem: A(396*KC*2) + 2*(KC*384)
    cudaFuncSetAttribute(conv_mma_k<64>,  cudaFuncAttributeMaxDynamicSharedMemorySize, 99840);
    cudaFuncSetAttribute(conv_mma_k<128>, cudaFuncAttributeMaxDynamicSharedMemorySize, 199680);

    // zero padded planes + c state (borders must be 0)
    cudaMemsetAsync(x16, 0, sizeof(__nv_bfloat16)*(size_t)NIMGX*PIMG*64);
    cudaMemsetAsync(h16, 0, sizeof(__nv_bfloat16)*(size_t)BB*PIMG*128);
    cudaMemsetAsync(cst, 0, sizeof(float)*(size_t)BB*HIDC*PP);

    prep_x_k<<<dim3(128, NIMGX), 256>>>(x);
    prep_w_k<<<(256*96*9 + 255)/256, 256>>>(wconv);

    // fork: conv_x runs per-timestep chunks on low-priority stream s2
    cudaEventRecord(evFork, 0);
    cudaStreamWaitEvent(s2, evFork, 0);
    for (int t = 0; t < TT; ++t) {
        // images b*TT + t for b = 0..7  ->  img = blockIdx.z*TT + t
        conv_mma_k<64><<<dim3(16, 2, BB), 256, 99840, s2>>>(
            (const __nv_bfloat16*)x16, (const __nv_bfloat16*)wxB1,
            (const __nv_bfloat16*)wxB2, (float*)ccx, TT, t);
        cudaEventRecord(evX[t], s2);
    }

    // recurrence on default stream; gatepack(t) joins conv_x chunk t
    for (int t = 0; t < TT; ++t) {
        conv_mma_k<128><<<dim3(16, 2, BB), 256, 199680>>>(
            (const __nv_bfloat16*)h16, (const __nv_bfloat16*)whB1,
            (const __nv_bfloat16*)whB2, (float*)cch, 1, 0);
        cudaStreamWaitEvent(0, evX[t], 0);
        gatepack_k<<<dim3(128, BB), 256>>>(out, bconv, t);
    }

    // normalization
    red1_k<<<dim3(64, 32), 256>>>(out);
    red2_k<<<1, 64>>>();
    norm_k<<<(NOUT + 255)/256, 256>>>(out, gamma, beta);
}